// round 15
// baseline (speedup 1.0000x reference)
#include <cuda_runtime.h>
#include <cuda_fp16.h>
#include <cstdint>

#define NB    32
#define NPTS  2048
#define KNN   16
#define NTOT  (NB * NPTS)
#define CH    32
#define HALF  1024           // candidates per half
#define PPB   64             // points per block (x2 halves = 128 threads)
#define SLOT  32             // candidate slots per (point, half)

// Scratch (device globals: no allocation allowed in kernel_launch)
__device__ int   g_idx[NTOT * KNN];
__device__ float g_S1[NTOT * CH];
__device__ float g_R1[NTOT * CH];
__device__ float g_S2[NTOT * CH];
__device__ float g_R2[NTOT * CH];
__device__ float g_H[NTOT * CH];

typedef unsigned long long u64;
typedef unsigned int u32;
typedef unsigned short u16;

// ---------------------------------------------------------------------------
// packed f32x2 helpers
// ---------------------------------------------------------------------------
__device__ __forceinline__ u64 ffma2(u64 a, u64 b, u64 c) {
    u64 d; asm("fma.rn.f32x2 %0, %1, %2, %3;" : "=l"(d) : "l"(a), "l"(b), "l"(c)); return d;
}
__device__ __forceinline__ u64 pack2(float lo, float hi) {
    u64 d; asm("mov.b64 %0, {%1, %2};" : "=l"(d) : "f"(lo), "f"(hi)); return d;
}
__device__ __forceinline__ void unpack2(u64 v, float& lo, float& hi) {
    asm("mov.b64 {%0, %1}, %2;" : "=f"(lo), "=f"(hi) : "l"(v));
}

// ---------------------------------------------------------------------------
// small helpers
// ---------------------------------------------------------------------------
__device__ __forceinline__ void ce_f(float& a, float& b) {
    float lo = fminf(a, b), hi = fmaxf(a, b);
    a = lo; b = hi;
}
__device__ __forceinline__ void ce64(u64& a, u64& b) {
    u64 x = a, y = b;
    bool sw = (y < x);
    a = sw ? y : x;
    b = sw ? x : y;
}
__device__ __forceinline__ __half2 h2(u32 v) {
    return *reinterpret_cast<const __half2*>(&v);
}
__device__ __forceinline__ float dist2s(float x, float y, float z,
                                        float xi, float yi, float zi) {
    float dx = x - xi, dy = y - yi, dz = z - zi;
    return fmaf(dz, dz, fmaf(dy, dy, dx * dx));
}
// sorted-pair streaming update: (b0<=b1) keeps the 2 smallest seen
__device__ __forceinline__ void upd2(__half2& b0, __half2& b1, __half2 k) {
    __half2 mx = __hmax2(k, b0);
    b0 = __hmin2(k, b0);
    b1 = __hmin2(b1, mx);
}
// bitonic sort-16 ascending on float[16]
__device__ __forceinline__ void sort16(float* f) {
#pragma unroll
    for (int k = 2; k <= 16; k <<= 1) {
#pragma unroll
        for (int s = k >> 1; s > 0; s >>= 1) {
#pragma unroll
            for (int i = 0; i < 16; ++i) {
                int l = i ^ s;
                if (l > i) {
                    if ((i & k) == 0) ce_f(f[i], f[l]);
                    else              ce_f(f[l], f[i]);
                }
            }
        }
    }
}

// ---------------------------------------------------------------------------
// kNN. Block = 64 points x 2 candidate-halves (128 threads).
// Pass A: f16 dot-product keys streamed through 32 streams x top-2 per thread
//   (3 fma-pipe ops/packed key). kappa = exact 16th of the union of kept sets
//   (valid upper bound: each kept value is a real candidate key; truncation
//   only loosens kappa). Merge: per-group sort-16 + fold/clean.
// Pass B: collect j with key <= kappa + 2M into u16 slots.
// Pass C: exact f32 (d2,j) insertion top-16 + half merge (= jax.lax.top_k).
// ---------------------------------------------------------------------------
__global__ void __launch_bounds__(128, 6)
knn_kernel(const float* __restrict__ pos, int* __restrict__ idx_out) {
    __shared__ __align__(16) __half shx[NPTS], shy[NPTS], shz[NPTS], shw[NPTS];
    __shared__ __align__(16) u32 sbuf[128 * 17];   // 8704 B, aliased 3 ways

    const int b     = blockIdx.x >> 5;
    const int chunk = blockIdx.x & 31;
    const int base  = b * NPTS;
    const int tid   = threadIdx.x;
    const int half  = tid >> 6;
    const int lp    = tid & 63;
    const int li    = chunk * PPB + lp;
    const int j0    = half * HALF;

    for (int t = tid; t < NPTS; t += 128) {
        const float* p = pos + (base + t) * 3;
        float x = p[0], y = p[1], z = p[2];
        shx[t] = __float2half_rn(x);
        shy[t] = __float2half_rn(y);
        shz[t] = __float2half_rn(z);
        shw[t] = __float2half_rn(x * x + y * y + z * z);
    }
    const float xi = pos[(base + li) * 3 + 0];
    const float yi = pos[(base + li) * 3 + 1];
    const float zi = pos[(base + li) * 3 + 2];
    __syncthreads();

    const __half mtwo = __float2half_rn(-2.0f);
    const __half2 m2x = __half2half2(__hmul(__float2half_rn(xi), mtwo));
    const __half2 m2y = __half2half2(__hmul(__float2half_rn(yi), mtwo));
    const __half2 m2z = __half2half2(__hmul(__float2half_rn(zi), mtwo));

    // ---- Pass A: 32 streams x top-2 ----
    const __half2 HINF2 = __half2half2(__ushort_as_half(0x7C00));
    __half2 p0[4][4], p1[4][4];                 // sorted pairs per (group, slot)
#pragma unroll
    for (int g = 0; g < 4; ++g)
#pragma unroll
        for (int d = 0; d < 4; ++d) { p0[g][d] = HINF2; p1[g][d] = HINF2; }

#pragma unroll 1
    for (int tile = 0; tile < HALF / 32; ++tile) {
        const int jb = j0 + tile * 32;
#pragma unroll
        for (int g = 0; g < 4; ++g) {
            const int o = jb + 8 * g;
            uint4 xv = *reinterpret_cast<const uint4*>(&shx[o]);
            uint4 yv = *reinterpret_cast<const uint4*>(&shy[o]);
            uint4 zv = *reinterpret_cast<const uint4*>(&shz[o]);
            uint4 wv = *reinterpret_cast<const uint4*>(&shw[o]);
            __half2 k0 = __hfma2(h2(zv.x), m2z, __hfma2(h2(yv.x), m2y, __hfma2(h2(xv.x), m2x, h2(wv.x))));
            __half2 k1 = __hfma2(h2(zv.y), m2z, __hfma2(h2(yv.y), m2y, __hfma2(h2(xv.y), m2x, h2(wv.y))));
            __half2 k2 = __hfma2(h2(zv.z), m2z, __hfma2(h2(yv.z), m2y, __hfma2(h2(xv.z), m2x, h2(wv.z))));
            __half2 k3 = __hfma2(h2(zv.w), m2z, __hfma2(h2(yv.w), m2y, __hfma2(h2(xv.w), m2x, h2(wv.w))));
            upd2(p0[g][0], p1[g][0], k0);
            upd2(p0[g][1], p1[g][1], k1);
            upd2(p0[g][2], p1[g][2], k2);
            upd2(p0[g][3], p1[g][3], k3);
        }
    }

    // ---- merge kept 64 values -> this thread's sorted lowest-16 ----
    float acc[16];
#pragma unroll
    for (int g = 0; g < 4; ++g) {
        float f[16];
#pragma unroll
        for (int d = 0; d < 4; ++d) {
            f[4 * d + 0] = __low2float(p0[g][d]);
            f[4 * d + 1] = __high2float(p0[g][d]);
            f[4 * d + 2] = __low2float(p1[g][d]);
            f[4 * d + 3] = __high2float(p1[g][d]);
        }
        sort16(f);
        if (g == 0) {
#pragma unroll
            for (int i = 0; i < 16; ++i) acc[i] = f[i];
        } else {
#pragma unroll
            for (int i = 0; i < 16; ++i) acc[i] = fminf(acc[i], f[15 - i]);
#pragma unroll
            for (int s = 8; s > 0; s >>= 1) {
#pragma unroll
                for (int i = 0; i < 16; ++i) {
                    int l = i ^ s;
                    if (l > i) ce_f(acc[i], acc[l]);
                }
            }
        }
    }

    // publish sorted-16; kappa = 16th smallest of the 2-thread union
    float* skap = reinterpret_cast<float*>(sbuf);    // [128] stride 17 floats
#pragma unroll
    for (int q = 0; q < KNN; ++q) skap[tid * 17 + q] = acc[q];
    __syncthreads();

    float kap = -3.4e38f;
#pragma unroll
    for (int i = 0; i < KNN; ++i)
        kap = fmaxf(kap, fminf(skap[lp * 17 + i], skap[(lp + 64) * 17 + (KNN - 1 - i)]));

    const float r  = sqrtf(xi * xi + yi * yi + zi * zi);
    const float M  = 0.003f * (r + 1.6f) * (3.0f * r + 1.6f);
    const float T  = kap + 2.0f * M + 1e-3f;
    const __half2 T2 = __half2half2(__float2half_ru(T));
    __syncthreads();

    // reinit as u16 candidate slots [128] stride 34 (17 words; conflict-free)
    u16* sb16 = reinterpret_cast<u16*>(sbuf);
#pragma unroll
    for (int u = 0; u < SLOT; ++u) sb16[tid * 34 + u] = 0xFFFFu;
    __syncthreads();

    // ---- Pass B: collect candidates with key <= T from this half ----
    int cnt = 0;
    const int sb0 = tid * 34;
#pragma unroll 2
    for (int o = j0; o < j0 + HALF; o += 8) {
        uint4 xv = *reinterpret_cast<const uint4*>(&shx[o]);
        uint4 yv = *reinterpret_cast<const uint4*>(&shy[o]);
        uint4 zv = *reinterpret_cast<const uint4*>(&shz[o]);
        uint4 wv = *reinterpret_cast<const uint4*>(&shw[o]);
        __half2 k0 = __hfma2(h2(zv.x), m2z, __hfma2(h2(yv.x), m2y, __hfma2(h2(xv.x), m2x, h2(wv.x))));
        __half2 k1 = __hfma2(h2(zv.y), m2z, __hfma2(h2(yv.y), m2y, __hfma2(h2(xv.y), m2x, h2(wv.y))));
        __half2 k2 = __hfma2(h2(zv.z), m2z, __hfma2(h2(yv.z), m2y, __hfma2(h2(xv.z), m2x, h2(wv.z))));
        __half2 k3 = __hfma2(h2(zv.w), m2z, __hfma2(h2(yv.w), m2y, __hfma2(h2(xv.w), m2x, h2(wv.w))));
        u32 m0 = __hle2_mask(k0, T2);
        u32 m1 = __hle2_mask(k1, T2);
        u32 m2 = __hle2_mask(k2, T2);
        u32 m3 = __hle2_mask(k3, T2);
        if ((m0 | m1 | m2 | m3) == 0u) continue;
        if (m0 & 0x0000FFFFu) { if (cnt < SLOT) sb16[sb0 + cnt++] = (u16)(o + 0); }
        if (m0 & 0xFFFF0000u) { if (cnt < SLOT) sb16[sb0 + cnt++] = (u16)(o + 1); }
        if (m1 & 0x0000FFFFu) { if (cnt < SLOT) sb16[sb0 + cnt++] = (u16)(o + 2); }
        if (m1 & 0xFFFF0000u) { if (cnt < SLOT) sb16[sb0 + cnt++] = (u16)(o + 3); }
        if (m2 & 0x0000FFFFu) { if (cnt < SLOT) sb16[sb0 + cnt++] = (u16)(o + 4); }
        if (m2 & 0xFFFF0000u) { if (cnt < SLOT) sb16[sb0 + cnt++] = (u16)(o + 5); }
        if (m3 & 0x0000FFFFu) { if (cnt < SLOT) sb16[sb0 + cnt++] = (u16)(o + 6); }
        if (m3 & 0xFFFF0000u) { if (cnt < SLOT) sb16[sb0 + cnt++] = (u16)(o + 7); }
    }

    // ---- Pass C: exact f32 (d2, j) streaming-insertion top-16 ----
    u64 bst[KNN];
#pragma unroll
    for (int q = 0; q < KNN; ++q) bst[q] = 0xFFFFFFFFFFFFFFFFull;

#pragma unroll 1
    for (int u = 0; u < SLOT; ++u) {
        u32 jj = sb16[sb0 + u];
        if (jj == 0xFFFFu) break;
        const float* pj = pos + (base + (int)jj) * 3;
        float d2 = dist2s(pj[0], pj[1], pj[2], xi, yi, zi);
        u64 vk = ((u64)__float_as_uint(d2) << 32) | jj;
#pragma unroll
        for (int q = 0; q < KNN; ++q) {
            u64 mn = (vk < bst[q]) ? vk : bst[q];
            vk     = (vk < bst[q]) ? bst[q] : vk;
            bst[q] = mn;
        }
    }
    __syncthreads();

    // ---- merge halves: half1 publishes sorted-16 (u64 [64] stride 17) ----
    u64* sped = reinterpret_cast<u64*>(sbuf);
    if (half == 1) {
#pragma unroll
        for (int q = 0; q < KNN; ++q) sped[lp * 17 + q] = bst[q];
    }
    __syncthreads();
    if (half == 0) {
        u64 m[KNN];
#pragma unroll
        for (int i = 0; i < KNN; ++i) {
            u64 o = sped[lp * 17 + (KNN - 1 - i)];
            m[i] = (bst[i] < o) ? bst[i] : o;
        }
#pragma unroll
        for (int s = 8; s > 0; s >>= 1) {
#pragma unroll
            for (int i = 0; i < KNN; ++i) {
                int l = i ^ s;
                if (l > i) ce64(m[i], m[l]);
            }
        }
        const int gi = base + li;
#pragma unroll
        for (int q = 0; q < KNN; ++q)
            idx_out[gi * KNN + q] = base + (int)(u32)(m[q] & 0xFFFFFFFFull);
    }
}

// ---------------------------------------------------------------------------
// Prep for layer 1 (h == p): S1[j] = p_j@(Wh+Wr), R1[i] = p_i@Wr
// ---------------------------------------------------------------------------
__global__ void prep1_kernel(const float* __restrict__ pos,
                             const float* __restrict__ w1a,
                             float* __restrict__ S, float* __restrict__ R) {
    int t = blockIdx.x * blockDim.x + threadIdx.x;
    int node = t >> 5;
    int c    = t & 31;
    float x = pos[node * 3 + 0];
    float y = pos[node * 3 + 1];
    float z = pos[node * 3 + 2];
    float wr0 = w1a[3 * 32 + c], wr1 = w1a[4 * 32 + c], wr2 = w1a[5 * 32 + c];
    float wh0 = w1a[0 * 32 + c] + wr0;
    float wh1 = w1a[1 * 32 + c] + wr1;
    float wh2 = w1a[2 * 32 + c] + wr2;
    S[t] = x * wh0 + y * wh1 + z * wh2;
    R[t] = x * wr0 + y * wr1 + z * wr2;
}

// ---------------------------------------------------------------------------
// Prep for layer 2, 2-node interleave (R14 winner).
// ---------------------------------------------------------------------------
__global__ void __launch_bounds__(256)
prep2_kernel(const float* __restrict__ pos,
             const float* __restrict__ H,
             const float* __restrict__ w2a,
             float* __restrict__ S, float* __restrict__ R) {
    const int lane = threadIdx.x & 31;
    const int wid  = threadIdx.x >> 5;
    const int wpb  = blockDim.x >> 5;

    float wa[CH];
#pragma unroll
    for (int d = 0; d < CH; ++d) wa[d] = w2a[d * 32 + lane];
    const float wr0 = w2a[(32 + 0) * 32 + lane];
    const float wr1 = w2a[(32 + 1) * 32 + lane];
    const float wr2 = w2a[(32 + 2) * 32 + lane];

    for (int node = (blockIdx.x * wpb + wid) * 2; node < NTOT;
         node += gridDim.x * wpb * 2) {
        float x0 = pos[node * 3 + 0], y0 = pos[node * 3 + 1], z0 = pos[node * 3 + 2];
        float x1 = pos[(node + 1) * 3 + 0], y1 = pos[(node + 1) * 3 + 1], z1 = pos[(node + 1) * 3 + 2];
        float r0 = x0 * wr0 + y0 * wr1 + z0 * wr2;
        float r1 = x1 * wr0 + y1 * wr1 + z1 * wr2;
        float h0 = H[node * 32 + lane];
        float h1 = H[(node + 1) * 32 + lane];
        float a0 = r0, a1 = 0.0f, c0 = r1, c1 = 0.0f;
#pragma unroll
        for (int d = 0; d < CH; d += 2) {
            float h0a = __shfl_sync(0xffffffffu, h0, d + 0);
            float h0b = __shfl_sync(0xffffffffu, h0, d + 1);
            float h1a = __shfl_sync(0xffffffffu, h1, d + 0);
            float h1b = __shfl_sync(0xffffffffu, h1, d + 1);
            a0 = fmaf(h0a, wa[d + 0], a0);
            a1 = fmaf(h0b, wa[d + 1], a1);
            c0 = fmaf(h1a, wa[d + 0], c0);
            c1 = fmaf(h1b, wa[d + 1], c1);
        }
        S[node * 32 + lane]       = a0 + a1;
        S[(node + 1) * 32 + lane] = c0 + c1;
        R[node * 32 + lane]       = r0;
        R[(node + 1) * 32 + lane] = r1;
    }
}

// ---------------------------------------------------------------------------
// Edge MLP + max, half-row-exchange GEMV, 2 NODES PER WARP (R13/14 winner).
// ---------------------------------------------------------------------------
template <bool RELU_OUT>
__global__ void __launch_bounds__(256)
layer_kernel(const float* __restrict__ S,
             const float* __restrict__ R,
             const float* __restrict__ ba,
             const float* __restrict__ wb,
             const float* __restrict__ bb,
             const int* __restrict__ idx,
             float* __restrict__ out) {
    __shared__ __align__(16) float sE[8][2][KNN][36];
    const int lane = threadIdx.x & 31;
    const int wid  = threadIdx.x >> 5;
    const int grp  = lane >> 4;

    u64 wp_own[8], wp_par[8];
#pragma unroll
    for (int d = 0; d < 8; ++d) {
        int cc = grp * 16 + 2 * d;
        wp_own[d] = pack2(wb[cc * 32 + lane],        wb[(cc + 1) * 32 + lane]);
        wp_par[d] = pack2(wb[cc * 32 + (lane ^ 16)], wb[(cc + 1) * 32 + (lane ^ 16)]);
    }
    const float bav = ba[lane];
    const float bbv = bb[lane];

    for (int node = blockIdx.x * 16 + wid * 2; node < NTOT; node += gridDim.x * 16) {
        const float vb0 = bav - R[node * 32 + lane];
        const float vb1 = bav - R[(node + 1) * 32 + lane];
        const int myj0  = idx[node * KNN + (lane & 15)];
        const int myj1  = idx[(node + 1) * KNN + (lane & 15)];

#pragma unroll
        for (int k = 0; k < KNN; ++k) {
            int j0 = __shfl_sync(0xffffffffu, myj0, k);
            int j1 = __shfl_sync(0xffffffffu, myj1, k);
            sE[wid][0][k][lane] = fmaxf(S[j0 * 32 + lane] + vb0, 0.0f);
            sE[wid][1][k][lane] = fmaxf(S[j1 * 32 + lane] + vb1, 0.0f);
        }
        __syncwarp();

        float mx0 = -3.4e38f, mx1 = -3.4e38f;
#pragma unroll
        for (int k = 0; k < KNN; ++k) {
            const ulonglong2* e0 =
                reinterpret_cast<const ulonglong2*>(&sE[wid][0][k][grp * 16]);
            const ulonglong2* e1 =
                reinterpret_cast<const ulonglong2*>(&sE[wid][1][k][grp * 16]);
            u64 a0 = 0, b0 = 0, a1 = 0, b1 = 0;
#pragma unroll
            for (int d4 = 0; d4 < 4; ++d4) {
                ulonglong2 v0 = e0[d4];
                ulonglong2 v1 = e1[d4];
                a0 = ffma2(v0.x, wp_own[2 * d4 + 0], a0);
                a0 = ffma2(v0.y, wp_own[2 * d4 + 1], a0);
                b0 = ffma2(v0.x, wp_par[2 * d4 + 0], b0);
                b0 = ffma2(v0.y, wp_par[2 * d4 + 1], b0);
                a1 = ffma2(v1.x, wp_own[2 * d4 + 0], a1);
                a1 = ffma2(v1.y, wp_own[2 * d4 + 1], a1);
                b1 = ffma2(v1.x, wp_par[2 * d4 + 0], b1);
                b1 = ffma2(v1.y, wp_par[2 * d4 + 1], b1);
            }
            float lo, hi;
            unpack2(a0, lo, hi); float p0o = lo + hi;
            unpack2(b0, lo, hi); float p0p = lo + hi;
            unpack2(a1, lo, hi); float p1o = lo + hi;
            unpack2(b1, lo, hi); float p1p = lo + hi;
            float r0 = __shfl_xor_sync(0xffffffffu, p0p, 16);
            float r1 = __shfl_xor_sync(0xffffffffu, p1p, 16);
            mx0 = fmaxf(mx0, p0o + r0);
            mx1 = fmaxf(mx1, p1o + r1);
        }
        __syncwarp();

        float res0 = mx0 + bbv;
        float res1 = mx1 + bbv;
        if (RELU_OUT) { res0 = fmaxf(res0, 0.0f); res1 = fmaxf(res1, 0.0f); }
        out[node * 32 + lane]       = res0;
        out[(node + 1) * 32 + lane] = res1;
    }
}

// ---------------------------------------------------------------------------
extern "C" void kernel_launch(void* const* d_in, const int* in_sizes, int n_in,
                              void* d_out, int out_size) {
    const float* pos = (const float*)d_in[0];
    const float* w1a = (const float*)d_in[2];
    const float* b1a = (const float*)d_in[3];
    const float* w1b = (const float*)d_in[4];
    const float* b1b = (const float*)d_in[5];
    const float* w2a = (const float*)d_in[6];
    const float* b2a = (const float*)d_in[7];
    const float* w2b = (const float*)d_in[8];
    const float* b2b = (const float*)d_in[9];
    float* out = (float*)d_out;

    int*   idx; cudaGetSymbolAddress((void**)&idx, g_idx);
    float* S1;  cudaGetSymbolAddress((void**)&S1,  g_S1);
    float* R1;  cudaGetSymbolAddress((void**)&R1,  g_R1);
    float* S2;  cudaGetSymbolAddress((void**)&S2,  g_S2);
    float* R2;  cudaGetSymbolAddress((void**)&R2,  g_R2);
    float* H;   cudaGetSymbolAddress((void**)&H,   g_H);

    // 1. kNN graph
    knn_kernel<<<NB * 32, 128>>>(pos, idx);

    // 2. conv1
    prep1_kernel<<<(NTOT * CH) / 256, 256>>>(pos, w1a, S1, R1);
    layer_kernel<true><<<2048, 256>>>(S1, R1, b1a, w1b, b1b, idx, H);

    // 3. conv2
    prep2_kernel<<<1024, 256>>>(pos, H, w2a, S2, R2);
    layer_kernel<false><<<2048, 256>>>(S2, R2, b2a, w2b, b2b, idx, out);
}

// round 16
// speedup vs baseline: 1.0082x; 1.0082x over previous
#include <cuda_runtime.h>
#include <cuda_fp16.h>
#include <cstdint>

#define NB    32
#define NPTS  2048
#define KNN   16
#define NTOT  (NB * NPTS)
#define CH    32
#define HALF  1024           // candidates per half
#define PPB   64             // points per block (x2 halves = 128 threads)
#define SLOT  32             // candidate slots per (point, half)

// Scratch (device globals: no allocation allowed in kernel_launch)
__device__ int   g_idx[NTOT * KNN];
__device__ float g_S1[NTOT * CH];
__device__ float g_R1[NTOT * CH];
__device__ float g_S2[NTOT * CH];
__device__ float g_R2[NTOT * CH];
__device__ float g_H[NTOT * CH];

typedef unsigned long long u64;
typedef unsigned int u32;
typedef unsigned short u16;

// ---------------------------------------------------------------------------
// packed f32x2 helpers
// ---------------------------------------------------------------------------
__device__ __forceinline__ u64 ffma2(u64 a, u64 b, u64 c) {
    u64 d; asm("fma.rn.f32x2 %0, %1, %2, %3;" : "=l"(d) : "l"(a), "l"(b), "l"(c)); return d;
}
__device__ __forceinline__ u64 pack2(float lo, float hi) {
    u64 d; asm("mov.b64 %0, {%1, %2};" : "=l"(d) : "f"(lo), "f"(hi)); return d;
}
__device__ __forceinline__ void unpack2(u64 v, float& lo, float& hi) {
    asm("mov.b64 {%0, %1}, %2;" : "=f"(lo), "=f"(hi) : "l"(v));
}

// ---------------------------------------------------------------------------
// small helpers
// ---------------------------------------------------------------------------
__device__ __forceinline__ void ce2h(__half2& a, __half2& b) {
    __half2 lo = __hmin2(a, b), hi = __hmax2(a, b);
    a = lo; b = hi;
}
__device__ __forceinline__ void ce_f(float& a, float& b) {
    float lo = fminf(a, b), hi = fmaxf(a, b);
    a = lo; b = hi;
}
__device__ __forceinline__ void ce64(u64& a, u64& b) {
    u64 x = a, y = b;
    bool sw = (y < x);
    a = sw ? y : x;
    b = sw ? x : y;
}
__device__ __forceinline__ __half2 h2(u32 v) {
    return *reinterpret_cast<const __half2*>(&v);
}
__device__ __forceinline__ float dist2s(float x, float y, float z,
                                        float xi, float yi, float zi) {
    float dx = x - xi, dy = y - yi, dz = z - zi;
    return fmaf(dz, dz, fmaf(dy, dy, dx * dx));
}

// ---------------------------------------------------------------------------
// kNN (R14 winner, unchanged). Block = 64 points x 2 candidate-halves.
// ---------------------------------------------------------------------------
__global__ void __launch_bounds__(128, 6)
knn_kernel(const float* __restrict__ pos, int* __restrict__ idx_out) {
    __shared__ __align__(16) __half shx[NPTS], shy[NPTS], shz[NPTS], shw[NPTS];
    __shared__ __align__(16) u32 sbuf[128 * 17];   // 8704 B, aliased 3 ways

    const int b     = blockIdx.x >> 5;
    const int chunk = blockIdx.x & 31;
    const int base  = b * NPTS;
    const int tid   = threadIdx.x;
    const int half  = tid >> 6;
    const int lp    = tid & 63;
    const int li    = chunk * PPB + lp;
    const int j0    = half * HALF;

    for (int t = tid; t < NPTS; t += 128) {
        const float* p = pos + (base + t) * 3;
        float x = p[0], y = p[1], z = p[2];
        shx[t] = __float2half_rn(x);
        shy[t] = __float2half_rn(y);
        shz[t] = __float2half_rn(z);
        shw[t] = __float2half_rn(x * x + y * y + z * z);
    }
    const float xi = pos[(base + li) * 3 + 0];
    const float yi = pos[(base + li) * 3 + 1];
    const float zi = pos[(base + li) * 3 + 2];
    __syncthreads();

    const __half mtwo = __float2half_rn(-2.0f);
    const __half2 m2x = __half2half2(__hmul(__float2half_rn(xi), mtwo));
    const __half2 m2y = __half2half2(__hmul(__float2half_rn(yi), mtwo));
    const __half2 m2z = __half2half2(__hmul(__float2half_rn(zi), mtwo));

    // ---- Pass A: 8 streams x top-4 over this half ----
    const __half2 HINF2 = __half2half2(__ushort_as_half(0x7C00));
    __half2 best[4][4];
#pragma unroll
    for (int g = 0; g < 4; ++g)
#pragma unroll
        for (int d = 0; d < 4; ++d) best[g][d] = HINF2;

#pragma unroll 1
    for (int tile = 0; tile < HALF / 32; ++tile) {
        const int jb = j0 + tile * 32;
#pragma unroll
        for (int g = 0; g < 4; ++g) {
            const int o = jb + 8 * g;
            uint4 xv = *reinterpret_cast<const uint4*>(&shx[o]);
            uint4 yv = *reinterpret_cast<const uint4*>(&shy[o]);
            uint4 zv = *reinterpret_cast<const uint4*>(&shz[o]);
            uint4 wv = *reinterpret_cast<const uint4*>(&shw[o]);
            __half2 k0 = __hfma2(h2(zv.x), m2z, __hfma2(h2(yv.x), m2y, __hfma2(h2(xv.x), m2x, h2(wv.x))));
            __half2 k1 = __hfma2(h2(zv.y), m2z, __hfma2(h2(yv.y), m2y, __hfma2(h2(xv.y), m2x, h2(wv.y))));
            __half2 k2 = __hfma2(h2(zv.z), m2z, __hfma2(h2(yv.z), m2y, __hfma2(h2(xv.z), m2x, h2(wv.z))));
            __half2 k3 = __hfma2(h2(zv.w), m2z, __hfma2(h2(yv.w), m2y, __hfma2(h2(xv.w), m2x, h2(wv.w))));
            ce2h(k0, k1); ce2h(k3, k2);
            ce2h(k0, k2); ce2h(k1, k3);
            ce2h(k0, k1); ce2h(k2, k3);
            best[g][0] = __hmin2(best[g][0], k3);
            best[g][1] = __hmin2(best[g][1], k2);
            best[g][2] = __hmin2(best[g][2], k1);
            best[g][3] = __hmin2(best[g][3], k0);
            ce2h(best[g][0], best[g][2]); ce2h(best[g][1], best[g][3]);
            ce2h(best[g][0], best[g][1]); ce2h(best[g][2], best[g][3]);
        }
    }

    // sort 32 kept values ascending, keep lowest 16
    float v[32];
#pragma unroll
    for (int g = 0; g < 4; ++g)
#pragma unroll
        for (int d = 0; d < 4; ++d) {
            v[g * 8 + d]     = __low2float(best[g][d]);
            v[g * 8 + 4 + d] = __high2float(best[g][d]);
        }
#pragma unroll
    for (int k = 2; k <= 32; k <<= 1) {
#pragma unroll
        for (int s = k >> 1; s > 0; s >>= 1) {
#pragma unroll
            for (int i = 0; i < 32; ++i) {
                int l = i ^ s;
                if (l > i) {
                    if ((i & k) == 0) ce_f(v[i], v[l]);
                    else              ce_f(v[l], v[i]);
                }
            }
        }
    }

    // publish sorted-16; kappa = 16th smallest of the 2-thread union
    float* skap = reinterpret_cast<float*>(sbuf);    // [128] stride 17 floats
#pragma unroll
    for (int q = 0; q < KNN; ++q) skap[tid * 17 + q] = v[q];
    __syncthreads();

    float kap = -3.4e38f;
#pragma unroll
    for (int i = 0; i < KNN; ++i)
        kap = fmaxf(kap, fminf(skap[lp * 17 + i], skap[(lp + 64) * 17 + (KNN - 1 - i)]));

    const float r  = sqrtf(xi * xi + yi * yi + zi * zi);
    const float M  = 0.003f * (r + 1.6f) * (3.0f * r + 1.6f);
    const float T  = kap + 2.0f * M + 1e-3f;
    const __half2 T2 = __half2half2(__float2half_ru(T));
    __syncthreads();

    // reinit as u16 candidate slots [128] stride 34 (17 words; conflict-free)
    u16* sb16 = reinterpret_cast<u16*>(sbuf);
#pragma unroll
    for (int u = 0; u < SLOT; ++u) sb16[tid * 34 + u] = 0xFFFFu;
    __syncthreads();

    // ---- Pass B: collect candidates with key <= T from this half ----
    int cnt = 0;
    const int sb0 = tid * 34;
#pragma unroll 2
    for (int o = j0; o < j0 + HALF; o += 8) {
        uint4 xv = *reinterpret_cast<const uint4*>(&shx[o]);
        uint4 yv = *reinterpret_cast<const uint4*>(&shy[o]);
        uint4 zv = *reinterpret_cast<const uint4*>(&shz[o]);
        uint4 wv = *reinterpret_cast<const uint4*>(&shw[o]);
        __half2 k0 = __hfma2(h2(zv.x), m2z, __hfma2(h2(yv.x), m2y, __hfma2(h2(xv.x), m2x, h2(wv.x))));
        __half2 k1 = __hfma2(h2(zv.y), m2z, __hfma2(h2(yv.y), m2y, __hfma2(h2(xv.y), m2x, h2(wv.y))));
        __half2 k2 = __hfma2(h2(zv.z), m2z, __hfma2(h2(yv.z), m2y, __hfma2(h2(xv.z), m2x, h2(wv.z))));
        __half2 k3 = __hfma2(h2(zv.w), m2z, __hfma2(h2(yv.w), m2y, __hfma2(h2(xv.w), m2x, h2(wv.w))));
        u32 m0 = __hle2_mask(k0, T2);
        u32 m1 = __hle2_mask(k1, T2);
        u32 m2 = __hle2_mask(k2, T2);
        u32 m3 = __hle2_mask(k3, T2);
        if ((m0 | m1 | m2 | m3) == 0u) continue;
        if (m0 & 0x0000FFFFu) { if (cnt < SLOT) sb16[sb0 + cnt++] = (u16)(o + 0); }
        if (m0 & 0xFFFF0000u) { if (cnt < SLOT) sb16[sb0 + cnt++] = (u16)(o + 1); }
        if (m1 & 0x0000FFFFu) { if (cnt < SLOT) sb16[sb0 + cnt++] = (u16)(o + 2); }
        if (m1 & 0xFFFF0000u) { if (cnt < SLOT) sb16[sb0 + cnt++] = (u16)(o + 3); }
        if (m2 & 0x0000FFFFu) { if (cnt < SLOT) sb16[sb0 + cnt++] = (u16)(o + 4); }
        if (m2 & 0xFFFF0000u) { if (cnt < SLOT) sb16[sb0 + cnt++] = (u16)(o + 5); }
        if (m3 & 0x0000FFFFu) { if (cnt < SLOT) sb16[sb0 + cnt++] = (u16)(o + 6); }
        if (m3 & 0xFFFF0000u) { if (cnt < SLOT) sb16[sb0 + cnt++] = (u16)(o + 7); }
    }

    // ---- Pass C: exact f32 (d2, j) streaming-insertion top-16 ----
    u64 bst[KNN];
#pragma unroll
    for (int q = 0; q < KNN; ++q) bst[q] = 0xFFFFFFFFFFFFFFFFull;

#pragma unroll 1
    for (int u = 0; u < SLOT; ++u) {
        u32 jj = sb16[sb0 + u];
        if (jj == 0xFFFFu) break;
        const float* pj = pos + (base + (int)jj) * 3;
        float d2 = dist2s(pj[0], pj[1], pj[2], xi, yi, zi);
        u64 vk = ((u64)__float_as_uint(d2) << 32) | jj;
#pragma unroll
        for (int q = 0; q < KNN; ++q) {
            u64 mn = (vk < bst[q]) ? vk : bst[q];
            vk     = (vk < bst[q]) ? bst[q] : vk;
            bst[q] = mn;
        }
    }
    __syncthreads();

    // ---- merge halves: half1 publishes sorted-16 (u64 [64] stride 17) ----
    u64* sped = reinterpret_cast<u64*>(sbuf);
    if (half == 1) {
#pragma unroll
        for (int q = 0; q < KNN; ++q) sped[lp * 17 + q] = bst[q];
    }
    __syncthreads();
    if (half == 0) {
        u64 m[KNN];
#pragma unroll
        for (int i = 0; i < KNN; ++i) {
            u64 o = sped[lp * 17 + (KNN - 1 - i)];
            m[i] = (bst[i] < o) ? bst[i] : o;
        }
#pragma unroll
        for (int s = 8; s > 0; s >>= 1) {
#pragma unroll
            for (int i = 0; i < KNN; ++i) {
                int l = i ^ s;
                if (l > i) ce64(m[i], m[l]);
            }
        }
        const int gi = base + li;
#pragma unroll
        for (int q = 0; q < KNN; ++q)
            idx_out[gi * KNN + q] = base + (int)(u32)(m[q] & 0xFFFFFFFFull);
    }
}

// ---------------------------------------------------------------------------
// Prep for layer 1 (h == p): S1[j] = p_j@(Wh+Wr), R1[i] = p_i@Wr
// ---------------------------------------------------------------------------
__global__ void prep1_kernel(const float* __restrict__ pos,
                             const float* __restrict__ w1a,
                             float* __restrict__ S, float* __restrict__ R) {
    int t = blockIdx.x * blockDim.x + threadIdx.x;
    int node = t >> 5;
    int c    = t & 31;
    float x = pos[node * 3 + 0];
    float y = pos[node * 3 + 1];
    float z = pos[node * 3 + 2];
    float wr0 = w1a[3 * 32 + c], wr1 = w1a[4 * 32 + c], wr2 = w1a[5 * 32 + c];
    float wh0 = w1a[0 * 32 + c] + wr0;
    float wh1 = w1a[1 * 32 + c] + wr1;
    float wh2 = w1a[2 * 32 + c] + wr2;
    S[t] = x * wh0 + y * wh1 + z * wh2;
    R[t] = x * wr0 + y * wr1 + z * wr2;
}

// ---------------------------------------------------------------------------
// Prep for layer 2, 2-node interleave (R14 winner).
// ---------------------------------------------------------------------------
__global__ void __launch_bounds__(256)
prep2_kernel(const float* __restrict__ pos,
             const float* __restrict__ H,
             const float* __restrict__ w2a,
             float* __restrict__ S, float* __restrict__ R) {
    const int lane = threadIdx.x & 31;
    const int wid  = threadIdx.x >> 5;
    const int wpb  = blockDim.x >> 5;

    float wa[CH];
#pragma unroll
    for (int d = 0; d < CH; ++d) wa[d] = w2a[d * 32 + lane];
    const float wr0 = w2a[(32 + 0) * 32 + lane];
    const float wr1 = w2a[(32 + 1) * 32 + lane];
    const float wr2 = w2a[(32 + 2) * 32 + lane];

    for (int node = (blockIdx.x * wpb + wid) * 2; node < NTOT;
         node += gridDim.x * wpb * 2) {
        float x0 = pos[node * 3 + 0], y0 = pos[node * 3 + 1], z0 = pos[node * 3 + 2];
        float x1 = pos[(node + 1) * 3 + 0], y1 = pos[(node + 1) * 3 + 1], z1 = pos[(node + 1) * 3 + 2];
        float r0 = x0 * wr0 + y0 * wr1 + z0 * wr2;
        float r1 = x1 * wr0 + y1 * wr1 + z1 * wr2;
        float h0 = H[node * 32 + lane];
        float h1 = H[(node + 1) * 32 + lane];
        float a0 = r0, a1 = 0.0f, c0 = r1, c1 = 0.0f;
#pragma unroll
        for (int d = 0; d < CH; d += 2) {
            float h0a = __shfl_sync(0xffffffffu, h0, d + 0);
            float h0b = __shfl_sync(0xffffffffu, h0, d + 1);
            float h1a = __shfl_sync(0xffffffffu, h1, d + 0);
            float h1b = __shfl_sync(0xffffffffu, h1, d + 1);
            a0 = fmaf(h0a, wa[d + 0], a0);
            a1 = fmaf(h0b, wa[d + 1], a1);
            c0 = fmaf(h1a, wa[d + 0], c0);
            c1 = fmaf(h1b, wa[d + 1], c1);
        }
        S[node * 32 + lane]       = a0 + a1;
        S[(node + 1) * 32 + lane] = c0 + c1;
        R[node * 32 + lane]       = r0;
        R[(node + 1) * 32 + lane] = r1;
    }
}

// ---------------------------------------------------------------------------
// Edge MLP + max, half-row-exchange GEMV, 4 NODES PER WARP.
//  4-way interleave: ~64 outstanding S-row gathers per warp (near the ~55
//  per-warp MLP cap) + 4-way GEMV ILP. 128-thread blocks keep smem at 36.9KB.
//  Weights shared across nodes (16 u64 regs).
// ---------------------------------------------------------------------------
template <bool RELU_OUT>
__global__ void __launch_bounds__(128)
layer_kernel(const float* __restrict__ S,
             const float* __restrict__ R,
             const float* __restrict__ ba,
             const float* __restrict__ wb,
             const float* __restrict__ bb,
             const int* __restrict__ idx,
             float* __restrict__ out) {
    __shared__ __align__(16) float sE[4][4][KNN][36];   // 36,864 B
    const int lane = threadIdx.x & 31;
    const int wid  = threadIdx.x >> 5;                  // 0..3
    const int grp  = lane >> 4;

    u64 wp_own[8], wp_par[8];
#pragma unroll
    for (int d = 0; d < 8; ++d) {
        int cc = grp * 16 + 2 * d;
        wp_own[d] = pack2(wb[cc * 32 + lane],        wb[(cc + 1) * 32 + lane]);
        wp_par[d] = pack2(wb[cc * 32 + (lane ^ 16)], wb[(cc + 1) * 32 + (lane ^ 16)]);
    }
    const float bav = ba[lane];
    const float bbv = bb[lane];

    for (int node = (blockIdx.x * 4 + wid) * 4; node < NTOT;
         node += gridDim.x * 16) {
        float vb[4];
        int   myj[4];
#pragma unroll
        for (int n = 0; n < 4; ++n) {
            vb[n]  = bav - R[(node + n) * 32 + lane];
            myj[n] = idx[(node + n) * KNN + (lane & 15)];
        }

#pragma unroll
        for (int k = 0; k < KNN; ++k) {
            int j0 = __shfl_sync(0xffffffffu, myj[0], k);
            int j1 = __shfl_sync(0xffffffffu, myj[1], k);
            int j2 = __shfl_sync(0xffffffffu, myj[2], k);
            int j3 = __shfl_sync(0xffffffffu, myj[3], k);
            sE[wid][0][k][lane] = fmaxf(S[j0 * 32 + lane] + vb[0], 0.0f);
            sE[wid][1][k][lane] = fmaxf(S[j1 * 32 + lane] + vb[1], 0.0f);
            sE[wid][2][k][lane] = fmaxf(S[j2 * 32 + lane] + vb[2], 0.0f);
            sE[wid][3][k][lane] = fmaxf(S[j3 * 32 + lane] + vb[3], 0.0f);
        }
        __syncwarp();

        float mx[4] = {-3.4e38f, -3.4e38f, -3.4e38f, -3.4e38f};
#pragma unroll
        for (int k = 0; k < KNN; ++k) {
#pragma unroll
            for (int n = 0; n < 4; ++n) {
                const ulonglong2* e2 =
                    reinterpret_cast<const ulonglong2*>(&sE[wid][n][k][grp * 16]);
                u64 a = 0, b = 0;
#pragma unroll
                for (int d4 = 0; d4 < 4; ++d4) {
                    ulonglong2 ev = e2[d4];
                    a = ffma2(ev.x, wp_own[2 * d4 + 0], a);
                    a = ffma2(ev.y, wp_own[2 * d4 + 1], a);
                    b = ffma2(ev.x, wp_par[2 * d4 + 0], b);
                    b = ffma2(ev.y, wp_par[2 * d4 + 1], b);
                }
                float alo, ahi, blo, bhi;
                unpack2(a, alo, ahi);
                unpack2(b, blo, bhi);
                float p_own = alo + ahi;
                float p_par = blo + bhi;
                float recv  = __shfl_xor_sync(0xffffffffu, p_par, 16);
                mx[n] = fmaxf(mx[n], p_own + recv);
            }
        }
        __syncwarp();

#pragma unroll
        for (int n = 0; n < 4; ++n) {
            float res = mx[n] + bbv;
            if (RELU_OUT) res = fmaxf(res, 0.0f);
            out[(node + n) * 32 + lane] = res;
        }
    }
}

// ---------------------------------------------------------------------------
extern "C" void kernel_launch(void* const* d_in, const int* in_sizes, int n_in,
                              void* d_out, int out_size) {
    const float* pos = (const float*)d_in[0];
    const float* w1a = (const float*)d_in[2];
    const float* b1a = (const float*)d_in[3];
    const float* w1b = (const float*)d_in[4];
    const float* b1b = (const float*)d_in[5];
    const float* w2a = (const float*)d_in[6];
    const float* b2a = (const float*)d_in[7];
    const float* w2b = (const float*)d_in[8];
    const float* b2b = (const float*)d_in[9];
    float* out = (float*)d_out;

    int*   idx; cudaGetSymbolAddress((void**)&idx, g_idx);
    float* S1;  cudaGetSymbolAddress((void**)&S1,  g_S1);
    float* R1;  cudaGetSymbolAddress((void**)&R1,  g_R1);
    float* S2;  cudaGetSymbolAddress((void**)&S2,  g_S2);
    float* R2;  cudaGetSymbolAddress((void**)&R2,  g_R2);
    float* H;   cudaGetSymbolAddress((void**)&H,   g_H);

    // 1. kNN graph
    knn_kernel<<<NB * 32, 128>>>(pos, idx);

    // 2. conv1
    prep1_kernel<<<(NTOT * CH) / 256, 256>>>(pos, w1a, S1, R1);
    layer_kernel<true><<<2048, 128>>>(S1, R1, b1a, w1b, b1b, idx, H);

    // 3. conv2
    prep2_kernel<<<1024, 256>>>(pos, H, w2a, S2, R2);
    layer_kernel<false><<<2048, 128>>>(S2, R2, b2a, w2b, b2b, idx, out);
}

// round 17
// speedup vs baseline: 1.0148x; 1.0066x over previous
#include <cuda_runtime.h>
#include <cuda_fp16.h>
#include <cstdint>

#define NB    32
#define NPTS  2048
#define KNN   16
#define NTOT  (NB * NPTS)
#define CH    32
#define HALF  1024           // candidates per half
#define PPB   64             // points per block (x2 halves = 128 threads)
#define SLOT  32             // candidate slots per (point, half)

// Scratch (device globals: no allocation allowed in kernel_launch)
__device__ int   g_idx[NTOT * KNN];
__device__ float g_S1[NTOT * CH];
__device__ float g_R1[NTOT * CH];
__device__ float g_S2[NTOT * CH];
__device__ float g_R2[NTOT * CH];
__device__ float g_H[NTOT * CH];

typedef unsigned long long u64;
typedef unsigned int u32;
typedef unsigned short u16;

// ---------------------------------------------------------------------------
// packed f32x2 helpers
// ---------------------------------------------------------------------------
__device__ __forceinline__ u64 ffma2(u64 a, u64 b, u64 c) {
    u64 d; asm("fma.rn.f32x2 %0, %1, %2, %3;" : "=l"(d) : "l"(a), "l"(b), "l"(c)); return d;
}
__device__ __forceinline__ u64 pack2(float lo, float hi) {
    u64 d; asm("mov.b64 %0, {%1, %2};" : "=l"(d) : "f"(lo), "f"(hi)); return d;
}
__device__ __forceinline__ void unpack2(u64 v, float& lo, float& hi) {
    asm("mov.b64 {%0, %1}, %2;" : "=f"(lo), "=f"(hi) : "l"(v));
}

// ---------------------------------------------------------------------------
// small helpers
// ---------------------------------------------------------------------------
__device__ __forceinline__ void ce2h(__half2& a, __half2& b) {
    __half2 lo = __hmin2(a, b), hi = __hmax2(a, b);
    a = lo; b = hi;
}
__device__ __forceinline__ void ce_f(float& a, float& b) {
    float lo = fminf(a, b), hi = fmaxf(a, b);
    a = lo; b = hi;
}
__device__ __forceinline__ void ce64(u64& a, u64& b) {
    u64 x = a, y = b;
    bool sw = (y < x);
    a = sw ? y : x;
    b = sw ? x : y;
}
__device__ __forceinline__ __half2 h2(u32 v) {
    return *reinterpret_cast<const __half2*>(&v);
}
__device__ __forceinline__ float dist2s(float x, float y, float z,
                                        float xi, float yi, float zi) {
    float dx = x - xi, dy = y - yi, dz = z - zi;
    return fmaf(dz, dz, fmaf(dy, dy, dx * dx));
}

// ---------------------------------------------------------------------------
// kNN (R14 winner) + FUSED prep1 epilogue.
// Block = 64 points x 2 candidate-halves (128 threads).
// Epilogue: S1[j] = p_j@(Wh+Wr), R1[i] = p_i@Wr for this block's 64 points.
// ---------------------------------------------------------------------------
__global__ void __launch_bounds__(128, 6)
knn_kernel(const float* __restrict__ pos, int* __restrict__ idx_out,
           const float* __restrict__ w1a,
           float* __restrict__ S1, float* __restrict__ R1) {
    __shared__ __align__(16) __half shx[NPTS], shy[NPTS], shz[NPTS], shw[NPTS];
    __shared__ __align__(16) u32 sbuf[128 * 17];   // 8704 B, aliased 3 ways

    const int b     = blockIdx.x >> 5;
    const int chunk = blockIdx.x & 31;
    const int base  = b * NPTS;
    const int tid   = threadIdx.x;
    const int half  = tid >> 6;
    const int lp    = tid & 63;
    const int li    = chunk * PPB + lp;
    const int j0    = half * HALF;

    for (int t = tid; t < NPTS; t += 128) {
        const float* p = pos + (base + t) * 3;
        float x = p[0], y = p[1], z = p[2];
        shx[t] = __float2half_rn(x);
        shy[t] = __float2half_rn(y);
        shz[t] = __float2half_rn(z);
        shw[t] = __float2half_rn(x * x + y * y + z * z);
    }
    const float xi = pos[(base + li) * 3 + 0];
    const float yi = pos[(base + li) * 3 + 1];
    const float zi = pos[(base + li) * 3 + 2];
    __syncthreads();

    const __half mtwo = __float2half_rn(-2.0f);
    const __half2 m2x = __half2half2(__hmul(__float2half_rn(xi), mtwo));
    const __half2 m2y = __half2half2(__hmul(__float2half_rn(yi), mtwo));
    const __half2 m2z = __half2half2(__hmul(__float2half_rn(zi), mtwo));

    // ---- Pass A: 8 streams x top-4 over this half ----
    const __half2 HINF2 = __half2half2(__ushort_as_half(0x7C00));
    __half2 best[4][4];
#pragma unroll
    for (int g = 0; g < 4; ++g)
#pragma unroll
        for (int d = 0; d < 4; ++d) best[g][d] = HINF2;

#pragma unroll 1
    for (int tile = 0; tile < HALF / 32; ++tile) {
        const int jb = j0 + tile * 32;
#pragma unroll
        for (int g = 0; g < 4; ++g) {
            const int o = jb + 8 * g;
            uint4 xv = *reinterpret_cast<const uint4*>(&shx[o]);
            uint4 yv = *reinterpret_cast<const uint4*>(&shy[o]);
            uint4 zv = *reinterpret_cast<const uint4*>(&shz[o]);
            uint4 wv = *reinterpret_cast<const uint4*>(&shw[o]);
            __half2 k0 = __hfma2(h2(zv.x), m2z, __hfma2(h2(yv.x), m2y, __hfma2(h2(xv.x), m2x, h2(wv.x))));
            __half2 k1 = __hfma2(h2(zv.y), m2z, __hfma2(h2(yv.y), m2y, __hfma2(h2(xv.y), m2x, h2(wv.y))));
            __half2 k2 = __hfma2(h2(zv.z), m2z, __hfma2(h2(yv.z), m2y, __hfma2(h2(xv.z), m2x, h2(wv.z))));
            __half2 k3 = __hfma2(h2(zv.w), m2z, __hfma2(h2(yv.w), m2y, __hfma2(h2(xv.w), m2x, h2(wv.w))));
            ce2h(k0, k1); ce2h(k3, k2);
            ce2h(k0, k2); ce2h(k1, k3);
            ce2h(k0, k1); ce2h(k2, k3);
            best[g][0] = __hmin2(best[g][0], k3);
            best[g][1] = __hmin2(best[g][1], k2);
            best[g][2] = __hmin2(best[g][2], k1);
            best[g][3] = __hmin2(best[g][3], k0);
            ce2h(best[g][0], best[g][2]); ce2h(best[g][1], best[g][3]);
            ce2h(best[g][0], best[g][1]); ce2h(best[g][2], best[g][3]);
        }
    }

    // sort 32 kept values ascending, keep lowest 16
    float v[32];
#pragma unroll
    for (int g = 0; g < 4; ++g)
#pragma unroll
        for (int d = 0; d < 4; ++d) {
            v[g * 8 + d]     = __low2float(best[g][d]);
            v[g * 8 + 4 + d] = __high2float(best[g][d]);
        }
#pragma unroll
    for (int k = 2; k <= 32; k <<= 1) {
#pragma unroll
        for (int s = k >> 1; s > 0; s >>= 1) {
#pragma unroll
            for (int i = 0; i < 32; ++i) {
                int l = i ^ s;
                if (l > i) {
                    if ((i & k) == 0) ce_f(v[i], v[l]);
                    else              ce_f(v[l], v[i]);
                }
            }
        }
    }

    // publish sorted-16; kappa = 16th smallest of the 2-thread union
    float* skap = reinterpret_cast<float*>(sbuf);    // [128] stride 17 floats
#pragma unroll
    for (int q = 0; q < KNN; ++q) skap[tid * 17 + q] = v[q];
    __syncthreads();

    float kap = -3.4e38f;
#pragma unroll
    for (int i = 0; i < KNN; ++i)
        kap = fmaxf(kap, fminf(skap[lp * 17 + i], skap[(lp + 64) * 17 + (KNN - 1 - i)]));

    const float r  = sqrtf(xi * xi + yi * yi + zi * zi);
    const float M  = 0.003f * (r + 1.6f) * (3.0f * r + 1.6f);
    const float T  = kap + 2.0f * M + 1e-3f;
    const __half2 T2 = __half2half2(__float2half_ru(T));
    __syncthreads();

    // reinit as u16 candidate slots [128] stride 34 (17 words; conflict-free)
    u16* sb16 = reinterpret_cast<u16*>(sbuf);
#pragma unroll
    for (int u = 0; u < SLOT; ++u) sb16[tid * 34 + u] = 0xFFFFu;
    __syncthreads();

    // ---- Pass B: collect candidates with key <= T from this half ----
    int cnt = 0;
    const int sb0 = tid * 34;
#pragma unroll 2
    for (int o = j0; o < j0 + HALF; o += 8) {
        uint4 xv = *reinterpret_cast<const uint4*>(&shx[o]);
        uint4 yv = *reinterpret_cast<const uint4*>(&shy[o]);
        uint4 zv = *reinterpret_cast<const uint4*>(&shz[o]);
        uint4 wv = *reinterpret_cast<const uint4*>(&shw[o]);
        __half2 k0 = __hfma2(h2(zv.x), m2z, __hfma2(h2(yv.x), m2y, __hfma2(h2(xv.x), m2x, h2(wv.x))));
        __half2 k1 = __hfma2(h2(zv.y), m2z, __hfma2(h2(yv.y), m2y, __hfma2(h2(xv.y), m2x, h2(wv.y))));
        __half2 k2 = __hfma2(h2(zv.z), m2z, __hfma2(h2(yv.z), m2y, __hfma2(h2(xv.z), m2x, h2(wv.z))));
        __half2 k3 = __hfma2(h2(zv.w), m2z, __hfma2(h2(yv.w), m2y, __hfma2(h2(xv.w), m2x, h2(wv.w))));
        u32 m0 = __hle2_mask(k0, T2);
        u32 m1 = __hle2_mask(k1, T2);
        u32 m2 = __hle2_mask(k2, T2);
        u32 m3 = __hle2_mask(k3, T2);
        if ((m0 | m1 | m2 | m3) == 0u) continue;
        if (m0 & 0x0000FFFFu) { if (cnt < SLOT) sb16[sb0 + cnt++] = (u16)(o + 0); }
        if (m0 & 0xFFFF0000u) { if (cnt < SLOT) sb16[sb0 + cnt++] = (u16)(o + 1); }
        if (m1 & 0x0000FFFFu) { if (cnt < SLOT) sb16[sb0 + cnt++] = (u16)(o + 2); }
        if (m1 & 0xFFFF0000u) { if (cnt < SLOT) sb16[sb0 + cnt++] = (u16)(o + 3); }
        if (m2 & 0x0000FFFFu) { if (cnt < SLOT) sb16[sb0 + cnt++] = (u16)(o + 4); }
        if (m2 & 0xFFFF0000u) { if (cnt < SLOT) sb16[sb0 + cnt++] = (u16)(o + 5); }
        if (m3 & 0x0000FFFFu) { if (cnt < SLOT) sb16[sb0 + cnt++] = (u16)(o + 6); }
        if (m3 & 0xFFFF0000u) { if (cnt < SLOT) sb16[sb0 + cnt++] = (u16)(o + 7); }
    }

    // ---- Pass C: exact f32 (d2, j) streaming-insertion top-16 ----
    u64 bst[KNN];
#pragma unroll
    for (int q = 0; q < KNN; ++q) bst[q] = 0xFFFFFFFFFFFFFFFFull;

#pragma unroll 1
    for (int u = 0; u < SLOT; ++u) {
        u32 jj = sb16[sb0 + u];
        if (jj == 0xFFFFu) break;
        const float* pj = pos + (base + (int)jj) * 3;
        float d2 = dist2s(pj[0], pj[1], pj[2], xi, yi, zi);
        u64 vk = ((u64)__float_as_uint(d2) << 32) | jj;
#pragma unroll
        for (int q = 0; q < KNN; ++q) {
            u64 mn = (vk < bst[q]) ? vk : bst[q];
            vk     = (vk < bst[q]) ? bst[q] : vk;
            bst[q] = mn;
        }
    }
    __syncthreads();

    // ---- merge halves: half1 publishes sorted-16 (u64 [64] stride 17) ----
    u64* sped = reinterpret_cast<u64*>(sbuf);
    if (half == 1) {
#pragma unroll
        for (int q = 0; q < KNN; ++q) sped[lp * 17 + q] = bst[q];
    }
    __syncthreads();
    if (half == 0) {
        u64 m[KNN];
#pragma unroll
        for (int i = 0; i < KNN; ++i) {
            u64 o = sped[lp * 17 + (KNN - 1 - i)];
            m[i] = (bst[i] < o) ? bst[i] : o;
        }
#pragma unroll
        for (int s = 8; s > 0; s >>= 1) {
#pragma unroll
            for (int i = 0; i < KNN; ++i) {
                int l = i ^ s;
                if (l > i) ce64(m[i], m[l]);
            }
        }
        const int gi = base + li;
#pragma unroll
        for (int q = 0; q < KNN; ++q)
            idx_out[gi * KNN + q] = base + (int)(u32)(m[q] & 0xFFFFFFFFull);
    }

    // ---- FUSED prep1 epilogue: S1/R1 for this block's 64 points ----
    {
        const int ch = tid & 31;
        const float wr0 = w1a[3 * 32 + ch];
        const float wr1 = w1a[4 * 32 + ch];
        const float wr2 = w1a[5 * 32 + ch];
        const float wh0 = w1a[0 * 32 + ch] + wr0;
        const float wh1 = w1a[1 * 32 + ch] + wr1;
        const float wh2 = w1a[2 * 32 + ch] + wr2;
#pragma unroll
        for (int n = tid >> 5; n < PPB; n += 4) {
            const int node = base + chunk * PPB + n;
            float x = pos[node * 3 + 0];
            float y = pos[node * 3 + 1];
            float z = pos[node * 3 + 2];
            S1[node * 32 + ch] = x * wh0 + y * wh1 + z * wh2;
            R1[node * 32 + ch] = x * wr0 + y * wr1 + z * wr2;
        }
    }
}

// ---------------------------------------------------------------------------
// Prep for layer 2, half-row gmem GEMV + 2-node interleave:
//   S2[i] = h_i @ w2a[0:32] + p_i @ w2a[32:35];  R2[i] = p_i @ w2a[32:35]
// Lane L (grp=L>>4) reads only its 16-float half of H[node] (4 uniform
// LDG.128, L1-broadcast), computes own+partner channel partials, one
// shfl_xor(16) combine. Replaces the serial 16-step shfl chain.
// ---------------------------------------------------------------------------
__global__ void __launch_bounds__(256)
prep2_kernel(const float* __restrict__ pos,
             const float* __restrict__ H,
             const float* __restrict__ w2a,
             float* __restrict__ S, float* __restrict__ R) {
    const int lane = threadIdx.x & 31;
    const int wid  = threadIdx.x >> 5;
    const int grp  = lane >> 4;

    u64 wa_own[8], wa_par[8];
#pragma unroll
    for (int d = 0; d < 8; ++d) {
        int cc = grp * 16 + 2 * d;
        wa_own[d] = pack2(w2a[cc * 32 + lane],        w2a[(cc + 1) * 32 + lane]);
        wa_par[d] = pack2(w2a[cc * 32 + (lane ^ 16)], w2a[(cc + 1) * 32 + (lane ^ 16)]);
    }
    const float wr0 = w2a[(32 + 0) * 32 + lane];
    const float wr1 = w2a[(32 + 1) * 32 + lane];
    const float wr2 = w2a[(32 + 2) * 32 + lane];

    for (int node = (blockIdx.x * 8 + wid) * 2; node < NTOT;
         node += gridDim.x * 16) {
        const ulonglong2* h0 =
            reinterpret_cast<const ulonglong2*>(&H[node * 32 + grp * 16]);
        const ulonglong2* h1 =
            reinterpret_cast<const ulonglong2*>(&H[(node + 1) * 32 + grp * 16]);
        u64 a0 = 0, b0 = 0, a1 = 0, b1 = 0;
#pragma unroll
        for (int d4 = 0; d4 < 4; ++d4) {
            ulonglong2 v0 = h0[d4];
            ulonglong2 v1 = h1[d4];
            a0 = ffma2(v0.x, wa_own[2 * d4 + 0], a0);
            a0 = ffma2(v0.y, wa_own[2 * d4 + 1], a0);
            b0 = ffma2(v0.x, wa_par[2 * d4 + 0], b0);
            b0 = ffma2(v0.y, wa_par[2 * d4 + 1], b0);
            a1 = ffma2(v1.x, wa_own[2 * d4 + 0], a1);
            a1 = ffma2(v1.y, wa_own[2 * d4 + 1], a1);
            b1 = ffma2(v1.x, wa_par[2 * d4 + 0], b1);
            b1 = ffma2(v1.y, wa_par[2 * d4 + 1], b1);
        }
        float lo, hi;
        unpack2(a0, lo, hi); float p0o = lo + hi;
        unpack2(b0, lo, hi); float p0p = lo + hi;
        unpack2(a1, lo, hi); float p1o = lo + hi;
        unpack2(b1, lo, hi); float p1p = lo + hi;
        float r0v = __shfl_xor_sync(0xffffffffu, p0p, 16);
        float r1v = __shfl_xor_sync(0xffffffffu, p1p, 16);

        float x0 = pos[node * 3 + 0], y0 = pos[node * 3 + 1], z0 = pos[node * 3 + 2];
        float x1 = pos[(node + 1) * 3 + 0], y1 = pos[(node + 1) * 3 + 1], z1 = pos[(node + 1) * 3 + 2];
        float rr0 = x0 * wr0 + y0 * wr1 + z0 * wr2;
        float rr1 = x1 * wr0 + y1 * wr1 + z1 * wr2;

        S[node * 32 + lane]       = (p0o + r0v) + rr0;
        S[(node + 1) * 32 + lane] = (p1o + r1v) + rr1;
        R[node * 32 + lane]       = rr0;
        R[(node + 1) * 32 + lane] = rr1;
    }
}

// ---------------------------------------------------------------------------
// Edge MLP + max, half-row-exchange GEMV, 2 NODES PER WARP (R13/14 winner).
// ---------------------------------------------------------------------------
template <bool RELU_OUT>
__global__ void __launch_bounds__(256)
layer_kernel(const float* __restrict__ S,
             const float* __restrict__ R,
             const float* __restrict__ ba,
             const float* __restrict__ wb,
             const float* __restrict__ bb,
             const int* __restrict__ idx,
             float* __restrict__ out) {
    __shared__ __align__(16) float sE[8][2][KNN][36];
    const int lane = threadIdx.x & 31;
    const int wid  = threadIdx.x >> 5;
    const int grp  = lane >> 4;

    u64 wp_own[8], wp_par[8];
#pragma unroll
    for (int d = 0; d < 8; ++d) {
        int cc = grp * 16 + 2 * d;
        wp_own[d] = pack2(wb[cc * 32 + lane],        wb[(cc + 1) * 32 + lane]);
        wp_par[d] = pack2(wb[cc * 32 + (lane ^ 16)], wb[(cc + 1) * 32 + (lane ^ 16)]);
    }
    const float bav = ba[lane];
    const float bbv = bb[lane];

    for (int node = blockIdx.x * 16 + wid * 2; node < NTOT; node += gridDim.x * 16) {
        const float vb0 = bav - R[node * 32 + lane];
        const float vb1 = bav - R[(node + 1) * 32 + lane];
        const int myj0  = idx[node * KNN + (lane & 15)];
        const int myj1  = idx[(node + 1) * KNN + (lane & 15)];

#pragma unroll
        for (int k = 0; k < KNN; ++k) {
            int j0 = __shfl_sync(0xffffffffu, myj0, k);
            int j1 = __shfl_sync(0xffffffffu, myj1, k);
            sE[wid][0][k][lane] = fmaxf(S[j0 * 32 + lane] + vb0, 0.0f);
            sE[wid][1][k][lane] = fmaxf(S[j1 * 32 + lane] + vb1, 0.0f);
        }
        __syncwarp();

        float mx0 = -3.4e38f, mx1 = -3.4e38f;
#pragma unroll
        for (int k = 0; k < KNN; ++k) {
            const ulonglong2* e0 =
                reinterpret_cast<const ulonglong2*>(&sE[wid][0][k][grp * 16]);
            const ulonglong2* e1 =
                reinterpret_cast<const ulonglong2*>(&sE[wid][1][k][grp * 16]);
            u64 a0 = 0, b0 = 0, a1 = 0, b1 = 0;
#pragma unroll
            for (int d4 = 0; d4 < 4; ++d4) {
                ulonglong2 v0 = e0[d4];
                ulonglong2 v1 = e1[d4];
                a0 = ffma2(v0.x, wp_own[2 * d4 + 0], a0);
                a0 = ffma2(v0.y, wp_own[2 * d4 + 1], a0);
                b0 = ffma2(v0.x, wp_par[2 * d4 + 0], b0);
                b0 = ffma2(v0.y, wp_par[2 * d4 + 1], b0);
                a1 = ffma2(v1.x, wp_own[2 * d4 + 0], a1);
                a1 = ffma2(v1.y, wp_own[2 * d4 + 1], a1);
                b1 = ffma2(v1.x, wp_par[2 * d4 + 0], b1);
                b1 = ffma2(v1.y, wp_par[2 * d4 + 1], b1);
            }
            float lo, hi;
            unpack2(a0, lo, hi); float p0o = lo + hi;
            unpack2(b0, lo, hi); float p0p = lo + hi;
            unpack2(a1, lo, hi); float p1o = lo + hi;
            unpack2(b1, lo, hi); float p1p = lo + hi;
            float r0 = __shfl_xor_sync(0xffffffffu, p0p, 16);
            float r1 = __shfl_xor_sync(0xffffffffu, p1p, 16);
            mx0 = fmaxf(mx0, p0o + r0);
            mx1 = fmaxf(mx1, p1o + r1);
        }
        __syncwarp();

        float res0 = mx0 + bbv;
        float res1 = mx1 + bbv;
        if (RELU_OUT) { res0 = fmaxf(res0, 0.0f); res1 = fmaxf(res1, 0.0f); }
        out[node * 32 + lane]       = res0;
        out[(node + 1) * 32 + lane] = res1;
    }
}

// ---------------------------------------------------------------------------
extern "C" void kernel_launch(void* const* d_in, const int* in_sizes, int n_in,
                              void* d_out, int out_size) {
    const float* pos = (const float*)d_in[0];
    const float* w1a = (const float*)d_in[2];
    const float* b1a = (const float*)d_in[3];
    const float* w1b = (const float*)d_in[4];
    const float* b1b = (const float*)d_in[5];
    const float* w2a = (const float*)d_in[6];
    const float* b2a = (const float*)d_in[7];
    const float* w2b = (const float*)d_in[8];
    const float* b2b = (const float*)d_in[9];
    float* out = (float*)d_out;

    int*   idx; cudaGetSymbolAddress((void**)&idx, g_idx);
    float* S1;  cudaGetSymbolAddress((void**)&S1,  g_S1);
    float* R1;  cudaGetSymbolAddress((void**)&R1,  g_R1);
    float* S2;  cudaGetSymbolAddress((void**)&S2,  g_S2);
    float* R2;  cudaGetSymbolAddress((void**)&R2,  g_R2);
    float* H;   cudaGetSymbolAddress((void**)&H,   g_H);

    // 1. kNN graph + fused prep1
    knn_kernel<<<NB * 32, 128>>>(pos, idx, w1a, S1, R1);

    // 2. conv1
    layer_kernel<true><<<2048, 256>>>(S1, R1, b1a, w1b, b1b, idx, H);

    // 3. conv2
    prep2_kernel<<<1024, 256>>>(pos, H, w2a, S2, R2);
    layer_kernel<false><<<2048, 256>>>(S2, R2, b2a, w2b, b2b, idx, out);
}